// round 1
// baseline (speedup 1.0000x reference)
#include <cuda_runtime.h>
#include <stdint.h>

// ---------------------------------------------------------------------------
// SSD head: per level i, inputs (metadata order):
//   d_in[5i+0] feat_i   [32, C_i, S_i, S_i]      float32
//   d_in[5i+1] cls_w_i  [91*A_i, C_i, 3, 3]      float32
//   d_in[5i+2] cls_b_i  [91*A_i]                 float32
//   d_in[5i+3] reg_w_i  [4*A_i, C_i, 3, 3]       float32
//   d_in[5i+4] reg_b_i  [4*A_i]                  float32
// Output (d_out, float32): bbox [32,8732,4] then cls [32,8732,91].
// ---------------------------------------------------------------------------

#define BATCH 32
#define NPOS  8732
#define CLS_OFF ((size_t)BATCH * NPOS * 4)

// packed weights scratch: [tap][c][o] per level, o = reg(0..4A) then cls
__device__ float g_wp[12695040];

// ------------------------- weight pack kernel -----------------------------
__global__ void pack_w_kernel(const float* __restrict__ regw,
                              const float* __restrict__ clsw,
                              size_t woff, int C, int A4, int Otot, int total) {
    int idx = blockIdx.x * blockDim.x + threadIdx.x;
    if (idx >= total) return;
    int o   = idx % Otot;
    int rc  = idx / Otot;
    int c   = rc % C;
    int tap = rc / C;
    float v;
    if (o < A4) v = regw[((size_t)o * C + c) * 9 + tap];
    else        v = clsw[((size_t)(o - A4) * C + c) * 9 + tap];
    g_wp[woff + idx] = v;
}

// ------------------------- fused conv GEMM kernel --------------------------
// Implicit GEMM: M = H*W (spatial, per image), N = Otot (= 95*A), K = C*9.
// Tile 128x128x8, 256 threads, 8x8 per thread (split 4+4 register blocking).
__global__ __launch_bounds__(256, 2)
void conv_gemm_kernel(const float* __restrict__ x,       // [32,C,H,W]
                      size_t woff,                        // into g_wp
                      const float* __restrict__ regb,
                      const float* __restrict__ clsb,
                      float* __restrict__ out,
                      int C, int H, int W, int A, int Otot, int P, int M) {
    const int n  = blockIdx.z;
    const int m0 = blockIdx.y * 128;
    const int o0 = blockIdx.x * 128;
    const int t  = threadIdx.x;
    const int tx = t & 15;
    const int ty = t >> 4;

    __shared__ float As[8][128];
    __shared__ float Bs[8][128];

    // A-load mapping: one spatial position per thread (column), 4 c-rows
    const int mA  = t & 127;
    const int c0  = t >> 7;       // 0 or 1
    const int p   = m0 + mA;
    const int pm  = (p < M) ? p : 0;
    const int h   = pm / W;
    const int w   = pm - h * W;
    const size_t HW = (size_t)H * W;
    const float* xbase = x + (size_t)n * C * HW;

    // B-load mapping
    const int oB = o0 + (t & 127);
    const bool bvalid = (oB < Otot);
    const float* wlev = g_wp + woff;

    float acc[8][8];
#pragma unroll
    for (int i = 0; i < 8; i++)
#pragma unroll
        for (int j = 0; j < 8; j++) acc[i][j] = 0.f;

    for (int tap = 0; tap < 9; ++tap) {
        const int dy = tap / 3 - 1;
        const int dx = tap % 3 - 1;
        const int hh = h + dy;
        const int ww = w + dx;
        const bool avalid = (p < M) && (hh >= 0) && (hh < H) && (ww >= 0) && (ww < W);
        const float* aptr = xbase + (size_t)(avalid ? (hh * W + ww) : 0);
        const float* bptr = wlev + (size_t)tap * C * Otot + oB;

        for (int ck = 0; ck < C; ck += 8) {
#pragma unroll
            for (int i = 0; i < 4; i++) {
                const int c = c0 + 2 * i;
                As[c][mA]      = avalid ? aptr[(size_t)(ck + c) * HW] : 0.f;
                Bs[c][t & 127] = bvalid ? bptr[(size_t)(ck + c) * Otot] : 0.f;
            }
            __syncthreads();
#pragma unroll
            for (int k = 0; k < 8; k++) {
                float4 a0 = *(const float4*)&As[k][ty * 4];
                float4 a1 = *(const float4*)&As[k][64 + ty * 4];
                float4 b0 = *(const float4*)&Bs[k][tx * 4];
                float4 b1 = *(const float4*)&Bs[k][64 + tx * 4];
                float a[8] = {a0.x, a0.y, a0.z, a0.w, a1.x, a1.y, a1.z, a1.w};
                float b[8] = {b0.x, b0.y, b0.z, b0.w, b1.x, b1.y, b1.z, b1.w};
#pragma unroll
                for (int i = 0; i < 8; i++)
#pragma unroll
                    for (int j = 0; j < 8; j++)
                        acc[i][j] = fmaf(a[i], b[j], acc[i][j]);
            }
            __syncthreads();
        }
    }

    // ---- epilogue: bias + scatter into [N, pos, cols] layout ----
    const int A4 = 4 * A;
    float* bbox = out;
    float* cls  = out + CLS_OFF;
#pragma unroll
    for (int i = 0; i < 8; i++) {
        const int mrow = (i < 4) ? (ty * 4 + i) : (64 + ty * 4 + (i - 4));
        const int pg = m0 + mrow;
        if (pg >= M) continue;
#pragma unroll
        for (int j = 0; j < 8; j++) {
            const int oc = o0 + ((j < 4) ? (tx * 4 + j) : (64 + tx * 4 + (j - 4)));
            if (oc >= Otot) continue;
            float v = acc[i][j];
            if (oc < A4) {
                v += regb[oc];
                const int a  = oc >> 2;
                const int ch = oc & 3;
                const size_t pos = (size_t)P + (size_t)pg * A + a;
                bbox[((size_t)n * NPOS + pos) * 4 + ch] = v;
            } else {
                const int q = oc - A4;
                v += clsb[q];
                const int a  = q / 91;
                const int ch = q - a * 91;
                const size_t pos = (size_t)P + (size_t)pg * A + a;
                cls[((size_t)n * NPOS + pos) * 91 + ch] = v;
            }
        }
    }
}

// ------------------------------- launch ------------------------------------
extern "C" void kernel_launch(void* const* d_in, const int* in_sizes, int n_in,
                              void* d_out, int out_size) {
    static const int    Cs[6]   = {512, 1024, 512, 256, 256, 256};
    static const int    Ss[6]   = {38, 19, 10, 5, 3, 1};
    static const int    Aa[6]   = {4, 6, 6, 6, 4, 4};
    static const int    Ps[6]   = {0, 5776, 7942, 8542, 8692, 8728};
    static const size_t WOFF[6] = {0, 1751040, 7004160, 9630720, 10944000, 11819520};

    float* out = (float*)d_out;

    // 1) pack weights into [tap][c][o] (reg first, then cls)
    for (int i = 0; i < 6; i++) {
        const int C = Cs[i], A = Aa[i];
        const int Otot = 95 * A, A4 = 4 * A;
        const int total = 9 * C * Otot;
        const float* clsw = (const float*)d_in[5 * i + 1];
        const float* regw = (const float*)d_in[5 * i + 3];
        pack_w_kernel<<<(total + 255) / 256, 256>>>(regw, clsw, WOFF[i], C, A4, Otot, total);
    }

    // 2) fused conv GEMM per level
    for (int i = 0; i < 6; i++) {
        const int C = Cs[i], S = Ss[i], A = Aa[i];
        const int Otot = 95 * A;
        const int M = S * S;
        const float* feat = (const float*)d_in[5 * i + 0];
        const float* clsb = (const float*)d_in[5 * i + 2];
        const float* regb = (const float*)d_in[5 * i + 4];
        dim3 grid((Otot + 127) / 128, (M + 127) / 128, BATCH);
        conv_gemm_kernel<<<grid, 256>>>(feat, WOFF[i], regb, clsb, out,
                                        C, S, S, A, Otot, Ps[i], M);
    }
}

// round 2
// speedup vs baseline: 1.0002x; 1.0002x over previous
#include <cuda_runtime.h>
#include <stdint.h>

// ---------------------------------------------------------------------------
// SSD head: per level i, inputs (metadata order):
//   d_in[5i+0] feat_i   [32, C_i, S_i, S_i]      float32
//   d_in[5i+1] cls_w_i  [91*A_i, C_i, 3, 3]      float32
//   d_in[5i+2] cls_b_i  [91*A_i]                 float32
//   d_in[5i+3] reg_w_i  [4*A_i, C_i, 3, 3]       float32
//   d_in[5i+4] reg_b_i  [4*A_i]                  float32
// Output (d_out, float32): bbox [32,8732,4] then cls [32,8732,91].
// ---------------------------------------------------------------------------

#define BATCH 32
#define NPOS  8732
#define CLS_OFF ((size_t)BATCH * NPOS * 4)

// packed weights scratch: [tap][c][o] per level, o = reg(0..4A) then cls
__device__ float g_wp[12695040];

// ------------------------- weight pack kernel -----------------------------
__global__ void pack_w_kernel(const float* __restrict__ regw,
                              const float* __restrict__ clsw,
                              size_t woff, int C, int A4, int Otot, int total) {
    int idx = blockIdx.x * blockDim.x + threadIdx.x;
    if (idx >= total) return;
    int o   = idx % Otot;
    int rc  = idx / Otot;
    int c   = rc % C;
    int tap = rc / C;
    float v;
    if (o < A4) v = regw[((size_t)o * C + c) * 9 + tap];
    else        v = clsw[((size_t)(o - A4) * C + c) * 9 + tap];
    g_wp[woff + idx] = v;
}

// ------------------------- fused conv GEMM kernel --------------------------
// Implicit GEMM: M = H*W (spatial, per image), N = Otot (= 95*A), K = C*9.
// Tile 128x128x8, 256 threads, 8x8 per thread (split 4+4 register blocking).
__global__ __launch_bounds__(256, 2)
void conv_gemm_kernel(const float* __restrict__ x,       // [32,C,H,W]
                      size_t woff,                        // into g_wp
                      const float* __restrict__ regb,
                      const float* __restrict__ clsb,
                      float* __restrict__ out,
                      int C, int H, int W, int A, int Otot, int P, int M) {
    const int n  = blockIdx.z;
    const int m0 = blockIdx.y * 128;
    const int o0 = blockIdx.x * 128;
    const int t  = threadIdx.x;
    const int tx = t & 15;
    const int ty = t >> 4;

    __shared__ float As[8][128];
    __shared__ float Bs[8][128];

    // A-load mapping: one spatial position per thread (column), 4 c-rows
    const int mA  = t & 127;
    const int c0  = t >> 7;       // 0 or 1
    const int p   = m0 + mA;
    const int pm  = (p < M) ? p : 0;
    const int h   = pm / W;
    const int w   = pm - h * W;
    const size_t HW = (size_t)H * W;
    const float* xbase = x + (size_t)n * C * HW;

    // B-load mapping
    const int oB = o0 + (t & 127);
    const bool bvalid = (oB < Otot);
    const float* wlev = g_wp + woff;

    float acc[8][8];
#pragma unroll
    for (int i = 0; i < 8; i++)
#pragma unroll
        for (int j = 0; j < 8; j++) acc[i][j] = 0.f;

    for (int tap = 0; tap < 9; ++tap) {
        const int dy = tap / 3 - 1;
        const int dx = tap % 3 - 1;
        const int hh = h + dy;
        const int ww = w + dx;
        const bool avalid = (p < M) && (hh >= 0) && (hh < H) && (ww >= 0) && (ww < W);
        const float* aptr = xbase + (size_t)(avalid ? (hh * W + ww) : 0);
        const float* bptr = wlev + (size_t)tap * C * Otot + oB;

        for (int ck = 0; ck < C; ck += 8) {
#pragma unroll
            for (int i = 0; i < 4; i++) {
                const int c = c0 + 2 * i;
                As[c][mA]      = avalid ? aptr[(size_t)(ck + c) * HW] : 0.f;
                Bs[c][t & 127] = bvalid ? bptr[(size_t)(ck + c) * Otot] : 0.f;
            }
            __syncthreads();
#pragma unroll
            for (int k = 0; k < 8; k++) {
                float4 a0 = *(const float4*)&As[k][ty * 4];
                float4 a1 = *(const float4*)&As[k][64 + ty * 4];
                float4 b0 = *(const float4*)&Bs[k][tx * 4];
                float4 b1 = *(const float4*)&Bs[k][64 + tx * 4];
                float a[8] = {a0.x, a0.y, a0.z, a0.w, a1.x, a1.y, a1.z, a1.w};
                float b[8] = {b0.x, b0.y, b0.z, b0.w, b1.x, b1.y, b1.z, b1.w};
#pragma unroll
                for (int i = 0; i < 8; i++)
#pragma unroll
                    for (int j = 0; j < 8; j++)
                        acc[i][j] = fmaf(a[i], b[j], acc[i][j]);
            }
            __syncthreads();
        }
    }

    // ---- epilogue: bias + scatter into [N, pos, cols] layout ----
    const int A4 = 4 * A;
    float* bbox = out;
    float* cls  = out + CLS_OFF;
#pragma unroll
    for (int i = 0; i < 8; i++) {
        const int mrow = (i < 4) ? (ty * 4 + i) : (64 + ty * 4 + (i - 4));
        const int pg = m0 + mrow;
        if (pg >= M) continue;
#pragma unroll
        for (int j = 0; j < 8; j++) {
            const int oc = o0 + ((j < 4) ? (tx * 4 + j) : (64 + tx * 4 + (j - 4)));
            if (oc >= Otot) continue;
            float v = acc[i][j];
            if (oc < A4) {
                v += regb[oc];
                const int a  = oc >> 2;
                const int ch = oc & 3;
                const size_t pos = (size_t)P + (size_t)pg * A + a;
                bbox[((size_t)n * NPOS + pos) * 4 + ch] = v;
            } else {
                const int q = oc - A4;
                v += clsb[q];
                const int a  = q / 91;
                const int ch = q - a * 91;
                const size_t pos = (size_t)P + (size_t)pg * A + a;
                cls[((size_t)n * NPOS + pos) * 91 + ch] = v;
            }
        }
    }
}

// ------------------------------- launch ------------------------------------
extern "C" void kernel_launch(void* const* d_in, const int* in_sizes, int n_in,
                              void* d_out, int out_size) {
    static const int    Cs[6]   = {512, 1024, 512, 256, 256, 256};
    static const int    Ss[6]   = {38, 19, 10, 5, 3, 1};
    static const int    Aa[6]   = {4, 6, 6, 6, 4, 4};
    static const int    Ps[6]   = {0, 5776, 7942, 8542, 8692, 8728};
    static const size_t WOFF[6] = {0, 1751040, 7004160, 9630720, 10944000, 11819520};

    float* out = (float*)d_out;

    // 1) pack weights into [tap][c][o] (reg first, then cls)
    for (int i = 0; i < 6; i++) {
        const int C = Cs[i], A = Aa[i];
        const int Otot = 95 * A, A4 = 4 * A;
        const int total = 9 * C * Otot;
        const float* clsw = (const float*)d_in[5 * i + 1];
        const float* regw = (const float*)d_in[5 * i + 3];
        pack_w_kernel<<<(total + 255) / 256, 256>>>(regw, clsw, WOFF[i], C, A4, Otot, total);
    }

    // 2) fused conv GEMM per level
    for (int i = 0; i < 6; i++) {
        const int C = Cs[i], S = Ss[i], A = Aa[i];
        const int Otot = 95 * A;
        const int M = S * S;
        const float* feat = (const float*)d_in[5 * i + 0];
        const float* clsb = (const float*)d_in[5 * i + 2];
        const float* regb = (const float*)d_in[5 * i + 4];
        dim3 grid((Otot + 127) / 128, (M + 127) / 128, BATCH);
        conv_gemm_kernel<<<grid, 256>>>(feat, WOFF[i], regb, clsb, out,
                                        C, S, S, A, Otot, Ps[i], M);
    }
}

// round 4
// speedup vs baseline: 2.9317x; 2.9311x over previous
#include <cuda_runtime.h>
#include <cuda_bf16.h>
#include <stdint.h>

#define BATCH 32
#define NPOS  8732
#define CLS_OFF ((size_t)BATCH * NPOS * 4)

// static scratch (no allocs)
__device__ __nv_bfloat16 g_xt_hi[37412864];
__device__ __nv_bfloat16 g_xt_lo[37412864];
__device__ __nv_bfloat16 g_wt_hi[12695040];
__device__ __nv_bfloat16 g_wt_lo[12695040];

__device__ __forceinline__ uint32_t smem_u32(const void* p) {
    uint32_t r;
    asm("{ .reg .u64 t; cvta.to.shared.u64 t, %1; cvt.u32.u64 %0, t; }" : "=r"(r) : "l"(p));
    return r;
}
__device__ __forceinline__ void cp16(uint32_t dst, const void* src, uint32_t sz) {
    asm volatile("cp.async.cg.shared.global [%0], [%1], 16, %2;"
                 :: "r"(dst), "l"(src), "r"(sz) : "memory");
}
__device__ __forceinline__ void cp_commit() { asm volatile("cp.async.commit_group;" ::: "memory"); }
__device__ __forceinline__ void cp_wait1()  { asm volatile("cp.async.wait_group 1;" ::: "memory"); }
__device__ __forceinline__ void cp_wait0()  { asm volatile("cp.async.wait_group 0;" ::: "memory"); }
__device__ __forceinline__ void ldsm4(uint32_t* r, uint32_t a) {
    asm volatile("ldmatrix.sync.aligned.m8n8.x4.shared.b16 {%0,%1,%2,%3}, [%4];"
                 : "=r"(r[0]), "=r"(r[1]), "=r"(r[2]), "=r"(r[3]) : "r"(a));
}
__device__ __forceinline__ void mma_bf16(float* d, const uint32_t* a, uint32_t b0, uint32_t b1) {
    asm volatile("mma.sync.aligned.m16n8k16.row.col.f32.bf16.bf16.f32 "
                 "{%0,%1,%2,%3}, {%4,%5,%6,%7}, {%8,%9}, {%0,%1,%2,%3};"
                 : "+f"(d[0]), "+f"(d[1]), "+f"(d[2]), "+f"(d[3])
                 : "r"(a[0]), "r"(a[1]), "r"(a[2]), "r"(a[3]), "r"(b0), "r"(b1));
}

// ---- prep 1: activation transpose [n][c][p] -> [n][p][c], bf16 split ----
__global__ void transpose_kernel(const float* __restrict__ x, size_t xoff, int C, int HW) {
    __shared__ float tile[32][33];
    const int n = blockIdx.z, p0 = blockIdx.x * 32, c0 = blockIdx.y * 32;
    const int tx = threadIdx.x, ty = threadIdx.y;
    const float* xb = x + (size_t)n * C * HW;
#pragma unroll
    for (int k = 0; k < 4; k++) {
        int c = c0 + ty + 8 * k, p = p0 + tx;
        tile[ty + 8 * k][tx] = (p < HW) ? xb[(size_t)c * HW + p] : 0.f;
    }
    __syncthreads();
#pragma unroll
    for (int k = 0; k < 4; k++) {
        int p = p0 + ty + 8 * k, c = c0 + tx;
        if (p < HW) {
            float v = tile[tx][ty + 8 * k];
            __nv_bfloat16 hi = __float2bfloat16(v);
            __nv_bfloat16 lo = __float2bfloat16(v - __bfloat162float(hi));
            size_t o = xoff + ((size_t)n * HW + p) * C + c;
            g_xt_hi[o] = hi; g_xt_lo[o] = lo;
        }
    }
}

// ---- prep 2: weights -> [tap][o][c], bf16 split (o = reg then cls) ----
__global__ void pack_w_kernel(const float* __restrict__ regw, const float* __restrict__ clsw,
                              size_t woff, int C, int A4, int Otot) {
    int idx = blockIdx.x * blockDim.x + threadIdx.x;
    if (idx >= Otot * C) return;
    int c = idx % C, o = idx / C;
    const float* src = (o < A4) ? (regw + ((size_t)o * C + c) * 9)
                                : (clsw + ((size_t)(o - A4) * C + c) * 9);
#pragma unroll
    for (int tap = 0; tap < 9; tap++) {
        float v = src[tap];
        __nv_bfloat16 hi = __float2bfloat16(v);
        __nv_bfloat16 lo = __float2bfloat16(v - __bfloat162float(hi));
        size_t d = woff + ((size_t)tap * Otot + o) * C + c;
        g_wt_hi[d] = hi; g_wt_lo[d] = lo;
    }
}

// ---- main GEMM: mma.sync bf16 (3x split), 128x128 tile, kchunk 32 ----
// smem per stage (80B row stride): Ah 10240 | Al 10240 | Bh 10240 | Bl 10240
#define STG 40960
#define ROWB 80

__global__ __launch_bounds__(256, 2)
void gemm_kernel(size_t xoff, size_t woff,
                 const float* __restrict__ regb, const float* __restrict__ clsb,
                 float* __restrict__ out,
                 int C, int H, int W, int A, int Otot, int P, int M) {
    extern __shared__ char dsm[];
    const uint32_t sb = smem_u32(dsm);

    const int HW = H * W, KC = C >> 5, nchunks = 9 * KC;
    const int t = threadIdx.x, warp = t >> 5, lane = t & 31;
    const int m0 = blockIdx.y * 128, o0 = blockIdx.x * 128;
    const int MT = BATCH * M, A4 = 4 * A;
    const int mwarp = warp >> 2, nwarp = warp & 3;

    // ---- loader geometry: thread t handles row r = t>>1, 32B half (t&1) ----
    const int r = t >> 1, chalf = t & 1;
    // A row precompute
    const int ma = m0 + r;
    const bool avalid = (ma < MT);
    const int mm = avalid ? ma : 0;
    const int na = mm / M, pa = mm - na * M;
    const int ah_ = pa / W, aw_ = pa - ah_ * W;
    const size_t a_nbase = (size_t)na * HW * C;
    // B row precompute
    const int ob = o0 + r;
    const bool bvalid = (ob < Otot);
    const size_t b_obase = (size_t)(bvalid ? ob : 0) * C;
    const size_t OC = (size_t)Otot * C;
    const uint32_t dst_r = (uint32_t)r * ROWB + (uint32_t)chalf * 32;

    float acc[4][4][4];
#pragma unroll
    for (int i = 0; i < 4; i++)
#pragma unroll
        for (int j = 0; j < 4; j++)
#pragma unroll
            for (int k = 0; k < 4; k++) acc[i][j][k] = 0.f;

    // ldmatrix per-lane address components
    const uint32_t a_lmrow = (uint32_t)(mwarp * 64 + (lane & 15)) * ROWB + ((lane >> 4) * 16);
    const int nl = (lane & 7) + ((lane >> 4) << 3);
    const uint32_t b_lmrow = (uint32_t)(nwarp * 32 + nl) * ROWB + (((lane >> 3) & 1) * 16);

#define LOAD_CHUNK(ch, s) {                                                        \
    const int tap = (ch) / KC, ck = (ch) - tap * KC;                               \
    const int dy = tap / 3 - 1, dx = tap % 3 - 1;                                  \
    const int hh = ah_ + dy, ww = aw_ + dx;                                        \
    const bool aok = avalid && hh >= 0 && hh < H && ww >= 0 && ww < W;             \
    const size_t asrc = xoff + a_nbase + (size_t)(aok ? (hh * W + ww) : 0) * C     \
                        + (ck << 5) + chalf * 16;                                  \
    const size_t bsrc = woff + (size_t)tap * OC + b_obase + (ck << 5) + chalf * 16;\
    const uint32_t az = aok ? 16u : 0u, bz = bvalid ? 16u : 0u;                    \
    const uint32_t d0 = sb + (s) * STG + dst_r;                                    \
    cp16(d0,          g_xt_hi + asrc,     az);                                     \
    cp16(d0 + 16,     g_xt_hi + asrc + 8, az);                                     \
    cp16(d0 + 10240,      g_xt_lo + asrc,     az);                                 \
    cp16(d0 + 10240 + 16, g_xt_lo + asrc + 8, az);                                 \
    cp16(d0 + 20480,      g_wt_hi + bsrc,     bz);                                 \
    cp16(d0 + 20480 + 16, g_wt_hi + bsrc + 8, bz);                                 \
    cp16(d0 + 30720,      g_wt_lo + bsrc,     bz);                                 \
    cp16(d0 + 30720 + 16, g_wt_lo + bsrc + 8, bz);                                 \
    cp_commit(); }

    LOAD_CHUNK(0, 0)

    for (int ch = 0; ch < nchunks; ch++) {
        const int s = ch & 1;
        if (ch + 1 < nchunks) { LOAD_CHUNK(ch + 1, s ^ 1) cp_wait1(); }
        else cp_wait0();
        __syncthreads();

        const uint32_t base = sb + s * STG;
#pragma unroll
        for (int ks = 0; ks < 2; ks++) {
            const uint32_t ko = ks * 32;
            uint32_t ahf[4][4], alf[4][4], bhf[2][4], blf[2][4];
#pragma unroll
            for (int mt = 0; mt < 4; mt++) {
                ldsm4(ahf[mt], base + a_lmrow + mt * (16 * ROWB) + ko);
                ldsm4(alf[mt], base + 10240 + a_lmrow + mt * (16 * ROWB) + ko);
            }
#pragma unroll
            for (int bp = 0; bp < 2; bp++) {
                ldsm4(bhf[bp], base + 20480 + b_lmrow + bp * (16 * ROWB) + ko);
                ldsm4(blf[bp], base + 30720 + b_lmrow + bp * (16 * ROWB) + ko);
            }
#pragma unroll
            for (int mt = 0; mt < 4; mt++)
#pragma unroll
                for (int nt = 0; nt < 4; nt++) {
                    const int bp = nt >> 1, su = (nt & 1) * 2;
                    mma_bf16(acc[mt][nt], ahf[mt], bhf[bp][su], bhf[bp][su + 1]);
                    mma_bf16(acc[mt][nt], ahf[mt], blf[bp][su], blf[bp][su + 1]);
                    mma_bf16(acc[mt][nt], alf[mt], bhf[bp][su], bhf[bp][su + 1]);
                }
        }
        __syncthreads();
    }

    // ---- epilogue: bias + scatter ----
    float* bbox = out;
    float* cls  = out + CLS_OFF;
#pragma unroll
    for (int mt = 0; mt < 4; mt++) {
#pragma unroll
        for (int half = 0; half < 2; half++) {
            const int m = m0 + mwarp * 64 + mt * 16 + (lane >> 2) + half * 8;
            if (m >= MT) continue;
            const int n = m / M, p = m - n * M;
            const size_t obase = (size_t)n * NPOS + P + (size_t)p * A;
#pragma unroll
            for (int nt = 0; nt < 4; nt++) {
#pragma unroll
                for (int e = 0; e < 2; e++) {
                    const int o = o0 + nwarp * 32 + nt * 8 + (lane & 3) * 2 + e;
                    if (o >= Otot) continue;
                    float v = acc[mt][nt][half * 2 + e];
                    if (o < A4) {
                        v += regb[o];
                        bbox[(obase + (o >> 2)) * 4 + (o & 3)] = v;
                    } else {
                        const int q = o - A4;
                        v += clsb[q];
                        const int a = q / 91;
                        cls[(obase + a) * 91 + (q - a * 91)] = v;
                    }
                }
            }
        }
    }
}

// ------------------------------- launch ------------------------------------
extern "C" void kernel_launch(void* const* d_in, const int* in_sizes, int n_in,
                              void* d_out, int out_size) {
    static const int    Cs[6]   = {512, 1024, 512, 256, 256, 256};
    static const int    Ss[6]   = {38, 19, 10, 5, 3, 1};
    static const int    Aa[6]   = {4, 6, 6, 6, 4, 4};
    static const int    Ps[6]   = {0, 5776, 7942, 8542, 8692, 8728};
    static const size_t XOFF[6] = {0, 23658496, 35487744, 37126144, 37330944, 37404672};
    static const size_t WOFF[6] = {0, 1751040, 7004160, 9630720, 10944000, 11819520};
    const int SMEM = 2 * STG;

    cudaFuncSetAttribute(gemm_kernel, cudaFuncAttributeMaxDynamicSharedMemorySize, SMEM);
    float* out = (float*)d_out;

    for (int i = 0; i < 6; i++) {
        const int C = Cs[i], S = Ss[i], A = Aa[i];
        const int HW = S * S, Otot = 95 * A, A4 = 4 * A;
        const float* feat = (const float*)d_in[5 * i + 0];
        const float* clsw = (const float*)d_in[5 * i + 1];
        const float* regw = (const float*)d_in[5 * i + 3];
        dim3 tg((HW + 31) / 32, C / 32, BATCH);
        transpose_kernel<<<tg, dim3(32, 8)>>>(feat, XOFF[i], C, HW);
        int tot = Otot * C;
        pack_w_kernel<<<(tot + 255) / 256, 256>>>(regw, clsw, WOFF[i], C, A4, Otot);
    }

    for (int i = 0; i < 6; i++) {
        const int C = Cs[i], S = Ss[i], A = Aa[i];
        const int Otot = 95 * A, M = S * S, MT = BATCH * M;
        const float* clsb = (const float*)d_in[5 * i + 2];
        const float* regb = (const float*)d_in[5 * i + 4];
        dim3 grid((Otot + 127) / 128, (MT + 127) / 128);
        gemm_kernel<<<grid, 256, SMEM>>>(XOFF[i], WOFF[i], regb, clsb, out,
                                         C, S, S, A, Otot, Ps[i], M);
    }
}